// round 15
// baseline (speedup 1.0000x reference)
#include <cuda_runtime.h>
#include <cstddef>

typedef unsigned long long u64;

// Problem constants
#define NB   1024
#define NT   1024
#define KQ   15
#define KT   20
#define NDOF 7

// Output layout offsets (fp32 elements), total = 38,827,009
static constexpr size_t OFF_MODEL       = 0;
static constexpr size_t OFF_QDOT_LOSS   = 1;
static constexpr size_t OFF_QDDOT_LOSS  = 1 + 7168;
static constexpr size_t OFF_QDDDOT_LOSS = 1 + 2 * 7168;
static constexpr size_t OFF_TORQUE_LOSS = 1 + 3 * 7168;
static constexpr size_t OFF_Q           = 1 + 4 * 7168;           // 28673 (== 1 mod 4)
static constexpr size_t QTD             = (size_t)NB * NT * NDOF; // 7,340,032
static constexpr size_t OFF_QDOT        = OFF_Q + QTD;
static constexpr size_t OFF_QDDOT       = OFF_Q + 2 * QTD;
static constexpr size_t OFF_QDDDOT      = OFF_Q + 3 * QTD;
static constexpr size_t OFF_TORQUE      = OFF_Q + 4 * QTD;
static constexpr size_t OFF_T           = OFF_Q + 5 * QTD;
static constexpr size_t OFF_TCUM        = OFF_T + NB;
static constexpr size_t OFF_DT          = OFF_TCUM + (size_t)NB * NT;

// ---- packed f32x2 helpers -------------------------------------------------
#define PACK2(out, lo, hi) \
    asm("mov.b64 %0, {%1, %2};" : "=l"(out) : "r"(__float_as_uint(lo)), "r"(__float_as_uint(hi)))
#define UNPACK2(lo, hi, in) do { unsigned int _ulo, _uhi; \
    asm("mov.b64 {%0, %1}, %2;" : "=r"(_ulo), "=r"(_uhi) : "l"(in)); \
    lo = __uint_as_float(_ulo); hi = __uint_as_float(_uhi); } while (0)
#define FMA2(d, a, b, c) asm("fma.rn.f32x2 %0, %1, %2, %3;" : "=l"(d) : "l"(a), "l"(b), "l"(c))
#define MUL2(d, a, b)    asm("mul.rn.f32x2 %0, %1, %2;"     : "=l"(d) : "l"(a), "l"(b))

__device__ __forceinline__ float huber_relu_dt(float v, float lim, float dt) {
    // huber(relu(|v| - lim), delta=1) * dt, branchless
    float r = fmaxf(fabsf(v) - lim, 0.0f);
    float m = fminf(r, 1.0f);
    return (r - 0.5f * m) * m * dt;
}

// ---------------------------------------------------------------------------
// Flush a staged 224-float chunk (data at buf[1..224]) to g (g%4 floats == 1):
// 55x STG.128 body + 4 scalar edges.
// ---------------------------------------------------------------------------
__device__ __forceinline__ void flush_chunk(float* __restrict__ g,
                                            const float* __restrict__ buf,
                                            int lane)
{
    float4 x0 = *(const float4*)(buf + 4 * (lane + 1));
    *(float4*)(g + 4 * (lane + 1) - 1) = x0;
    if (lane < 23) {
        float4 x1 = *(const float4*)(buf + 4 * (lane + 33));
        *(float4*)(g + 4 * (lane + 33) - 1) = x1;
    }
    if (lane < 3)       g[lane] = buf[lane + 1];
    else if (lane == 3) g[223]  = buf[224];
}

// ---------------------------------------------------------------------------
// Heterogeneous fused kernel. 3072 blocks x 256 threads.
//   bid % 3 in {0,1} -> main tile block (2048 of them; R13 two-phase body)
//   bid % 3 == 2     -> side block: dt + cumsum + t for batch g = bid/3
// Side work overlaps with the L1-bound main work instead of serializing.
// ---------------------------------------------------------------------------
#define T_TILE 64
#define B_TILE 8
#define THR    256

union SmemOverlay {
    float2 tbp[3][KT][32];            // 15360 B, prologue only
    float  stage[B_TILE][4][240];     // 30720 B, after sync
};

__global__ __launch_bounds__(THR, 3)
void fused_kernel(const float* __restrict__ q_cps, const float* __restrict__ t_cps,
                  const float* __restrict__ N,   const float* __restrict__ dN,
                  const float* __restrict__ ddN, const float* __restrict__ dddN,
                  const float* __restrict__ Nt,  const float* __restrict__ dNt,
                  const float* __restrict__ ddNt,
                  const float* __restrict__ Ldot, const float* __restrict__ Lddot,
                  const float* __restrict__ Ldddot,
                  float* __restrict__ out)
{
    __shared__ float2 s_qbp[4][KQ][32];                 // [plane][k][lt-pair]
    __shared__ SmemOverlay s_u;                         // tbp (prologue) / stage
    __shared__ __align__(16) u64 s_qcd[B_TILE][KQ][8];  // dup q_cps pairs; slot 7 pad
    __shared__ __align__(16) u64 s_tcd[B_TILE][KT];     // dup t_cps pairs
    __shared__ float  s_lims[24];
    __shared__ float  s_dt[B_TILE][64];                 // per-warp dt per t
    __shared__ float  s_zero[240];                      // block-wide zero chunk
    __shared__ float  s_model[B_TILE];
    __shared__ float  s_tc2[KT];                        // side: t_cps row
    __shared__ float  s_ws[8];                          // side: per-warp scan sums

    const int tid = threadIdx.x;
    const int bid = blockIdx.x;
    const int g   = bid / 3;
    const int r3  = bid - 3 * g;

    if (r3 == 2) {
        // ================= SIDE BLOCK: dt + cumsum + t for batch g ==========
        const int b = g;
        if (tid < KT) s_tc2[tid] = t_cps[b * KT + tid];
        __syncthreads();

        const int lane = tid & 31;
        const int wid  = tid >> 5;

        float dtv[4];
        float s = 0.0f;
#pragma unroll
        for (int j = 0; j < 4; j++) {
            const int t = 4 * tid + j;
            const float4* nr = (const float4*)(Nt + t * KT);  // 80B rows, 16B aligned
            float4 n0 = nr[0], n1 = nr[1], n2 = nr[2], n3 = nr[3], n4 = nr[4];
            float a0 = n0.x * s_tc2[0]  + n0.y * s_tc2[1]  + n0.z * s_tc2[2]  + n0.w * s_tc2[3];
            float a1 = n1.x * s_tc2[4]  + n1.y * s_tc2[5]  + n1.z * s_tc2[6]  + n1.w * s_tc2[7];
            float a2 = n2.x * s_tc2[8]  + n2.y * s_tc2[9]  + n2.z * s_tc2[10] + n2.w * s_tc2[11];
            float a3 = n3.x * s_tc2[12] + n3.y * s_tc2[13] + n3.z * s_tc2[14] + n3.w * s_tc2[15];
            float a4 = n4.x * s_tc2[16] + n4.y * s_tc2[17] + n4.z * s_tc2[18] + n4.w * s_tc2[19];
            float a  = (a0 + a1) + (a2 + a3) + a4;
            dtv[j] = 1.0f / (a * (float)NT);
            s += dtv[j];
        }

        // inclusive warp scan of per-thread sums
        float v = s;
#pragma unroll
        for (int off = 1; off < 32; off <<= 1) {
            float u = __shfl_up_sync(0xffffffffu, v, off);
            if (lane >= off) v += u;
        }
        if (lane == 31) s_ws[wid] = v;
        __syncthreads();
        if (wid == 0 && lane < 8) {
            float wv = s_ws[lane];
#pragma unroll
            for (int off = 1; off < 8; off <<= 1) {
                float u = __shfl_up_sync(0x000000ffu, wv, off);
                if (lane >= off) wv += u;
            }
            s_ws[lane] = wv;
        }
        __syncthreads();
        float prefix = (v - s) + (wid > 0 ? s_ws[wid - 1] : 0.0f);

        float c0 = prefix + dtv[0];
        float c1 = c0 + dtv[1];
        float c2 = c1 + dtv[2];
        float c3 = c2 + dtv[3];

        const size_t rowD = OFF_DT   + (size_t)b * NT + 4 * tid;
        const size_t rowC = OFF_TCUM + (size_t)b * NT + 4 * tid;
        out[rowD + 0] = dtv[0]; out[rowD + 1] = dtv[1];
        out[rowD + 2] = dtv[2]; out[rowD + 3] = dtv[3];
        out[rowC + 0] = c0; out[rowC + 1] = c1;
        out[rowC + 2] = c2; out[rowC + 3] = c3;
        if (tid == THR - 1) out[OFF_T + b] = c3;
        return;
    }

    // ================= MAIN BLOCK (R13 two-phase body) =======================
    const int mid = 2 * g + r3;            // 0..2047
    const int t0  = (mid & 15) * T_TILE;   // 16 t-tiles
    const int b0  = (mid >> 4) * B_TILE;   // 128 b-tiles

    {
        const float* qa[4] = {N, dN, ddN, dddN};
        for (int idx = tid; idx < 4 * KQ * 32; idx += THR) {
            int p = idx / (KQ * 32), r = idx % (KQ * 32);
            int k = r / 32, lt = r % 32;
            const float* src = qa[p];
            s_qbp[p][k][lt] = make_float2(src[(t0 + lt) * KQ + k],
                                          src[(t0 + lt + 32) * KQ + k]);
        }
        const float* ta[3] = {Nt, dNt, ddNt};
        for (int idx = tid; idx < 3 * KT * 32; idx += THR) {
            int p = idx / (KT * 32), r = idx % (KT * 32);
            int k = r / 32, lt = r % 32;
            const float* src = ta[p];
            s_u.tbp[p][k][lt] = make_float2(src[(t0 + lt) * KT + k],
                                            src[(t0 + lt + 32) * KT + k]);
        }
    }
    for (int idx = tid; idx < B_TILE * KQ * NDOF; idx += THR) {
        int w = idx / (KQ * NDOF), r = idx % (KQ * NDOF);
        float c = q_cps[(size_t)b0 * KQ * NDOF + idx];
        u64 p; PACK2(p, c, c);
        s_qcd[w][r / NDOF][r % NDOF] = p;
    }
    for (int idx = tid; idx < B_TILE * KT; idx += THR) {
        float c = t_cps[b0 * KT + idx];
        u64 p; PACK2(p, c, c);
        s_tcd[idx / KT][idx % KT] = p;
    }
    for (int idx = tid; idx < 240; idx += THR) s_zero[idx] = 0.0f;
    if (tid < 7) {
        s_lims[tid]      = Ldot[tid];
        s_lims[7 + tid]  = Lddot[tid];
        s_lims[14 + tid] = Ldddot[tid];
    }
    __syncthreads();

    const int lane = tid & 31;
    const int w    = tid >> 5;   // local batch 0..7
    const int b    = b0 + w;

    // --- fused time-spline evaluation (packed; reads s_u.tbp) ---
    u64 ap = 0, ddp = 0, dddp = 0;
#pragma unroll
    for (int k = 0; k < KT; k += 2) {
        ulonglong2 tc2 = *(const ulonglong2*)&s_tcd[w][k];  // broadcast LDS.128
        FMA2(ap,   *(const u64*)&s_u.tbp[0][k][lane],     tc2.x, ap);
        FMA2(ddp,  *(const u64*)&s_u.tbp[1][k][lane],     tc2.x, ddp);
        FMA2(dddp, *(const u64*)&s_u.tbp[2][k][lane],     tc2.x, dddp);
        FMA2(ap,   *(const u64*)&s_u.tbp[0][k + 1][lane], tc2.y, ap);
        FMA2(ddp,  *(const u64*)&s_u.tbp[1][k + 1][lane], tc2.y, ddp);
        FMA2(dddp, *(const u64*)&s_u.tbp[2][k + 1][lane], tc2.y, dddp);
    }
    // packed coefficients (ddp/dddp die here)
    u64 a2p; MUL2(a2p, ap, ap);
    u64 a3p; MUL2(a3p, a2p, ap);
    u64 c1p; MUL2(c1p, ddp, ap);
    u64 c2p; { u64 t; MUL2(t, ddp, a2p); u64 th; PACK2(th, 3.0f, 3.0f); MUL2(c2p, th, t); }
    u64 c3p; { u64 t; MUL2(t, ddp, ddp); u64 t2; MUL2(t2, t, ap); FMA2(c3p, a2p, dddp, t2); }
    {
        float a0, a1; UNPACK2(a0, a1, ap);
        s_dt[w][lane]      = 1.0f / (a0 * (float)NT);
        s_dt[w][32 + lane] = 1.0f / (a1 * (float)NT);
    }

    // per-lane loss constants (lanes 0..27: d = lane>>2, g = lane&3)
    const int ld = lane >> 2;
    const int lg = lane & 3;
    float limA = 0.f, limB = 0.f, limC = 0.f;
    if (lane < 28) { limA = s_lims[ld]; limB = s_lims[7 + ld]; limC = s_lims[14 + ld]; }
    float acc1 = 0.f, acc2 = 0.f, acc3 = 0.f;

    const float* sdt = s_dt[w];
    const size_t chunk0 = ((size_t)b * NT + t0) * NDOF;       // multiple of 224
    const size_t chunk1 = chunk0 + 224;

    u64 W[7];   // v3 partial: qdd*c2 + qd*c3, carried into phase 2

    // ======== Merged phase 1: qd & qdd ========
    {
        u64 A[7], B2[7];
#pragma unroll
        for (int d = 0; d < 7; d++) { A[d] = 0; B2[d] = 0; }
#pragma unroll
        for (int k = 0; k < KQ; k++) {
            u64 nb1 = *(const u64*)&s_qbp[1][k][lane];
            u64 nb2 = *(const u64*)&s_qbp[2][k][lane];
            const ulonglong2* csp = (const ulonglong2*)&s_qcd[w][k][0];
            ulonglong2 p01 = csp[0], p23 = csp[1], p45 = csp[2], p67 = csp[3];
            u64 cs[7] = {p01.x, p01.y, p23.x, p23.y, p45.x, p45.y, p67.x};
#pragma unroll
            for (int d = 0; d < 7; d++) {
                FMA2(A[d],  nb1, cs[d], A[d]);
                FMA2(B2[d], nb2, cs[d], B2[d]);
            }
        }
        // tbp must be fully consumed block-wide before staging overwrites it
        __syncthreads();

        float* st0 = s_u.stage[w][0];
        float* st1 = s_u.stage[w][1];
        float* st2 = s_u.stage[w][2];
        float* st3 = s_u.stage[w][3];
#pragma unroll
        for (int d = 0; d < 7; d++) {
            u64 v1; MUL2(v1, A[d], ap);
            u64 t1; MUL2(t1, A[d], c1p);
            u64 v2; FMA2(v2, B2[d], a2p, t1);
            u64 t2; MUL2(t2, A[d], c3p);
            FMA2(W[d], B2[d], c2p, t2);

            float lo, hi;
            UNPACK2(lo, hi, v1);
            st0[1 + 7 * lane + d] = lo;   // conflict-free (gcd(7,32)=1)
            st1[1 + 7 * lane + d] = hi;
            UNPACK2(lo, hi, v2);
            st2[1 + 7 * lane + d] = lo;
            st3[1 + 7 * lane + d] = hi;
        }
        __syncwarp();
        flush_chunk(out + OFF_QDOT  + chunk0, st0, lane);
        flush_chunk(out + OFF_QDOT  + chunk1, st1, lane);
        flush_chunk(out + OFF_QDDOT + chunk0, st2, lane);
        flush_chunk(out + OFF_QDDOT + chunk1, st3, lane);
        if (lane < 28) {
#pragma unroll
            for (int j = 0; j < 8; j++) {
                int t8 = 8 * lg + j;
                acc1 += huber_relu_dt(st0[1 + 7 * t8 + ld], limA, sdt[t8]);
                acc1 += huber_relu_dt(st1[1 + 7 * t8 + ld], limA, sdt[32 + t8]);
                acc2 += huber_relu_dt(st2[1 + 7 * t8 + ld], limB, sdt[t8]);
                acc2 += huber_relu_dt(st3[1 + 7 * t8 + ld], limB, sdt[32 + t8]);
            }
        }
        __syncwarp();
    }

    // ======== Merged phase 2: qddd & q ========
    {
        u64 C[7], D[7];
#pragma unroll
        for (int d = 0; d < 7; d++) { C[d] = 0; D[d] = 0; }
#pragma unroll
        for (int k = 0; k < KQ; k++) {
            u64 nb3 = *(const u64*)&s_qbp[3][k][lane];
            u64 nb0 = *(const u64*)&s_qbp[0][k][lane];
            const ulonglong2* csp = (const ulonglong2*)&s_qcd[w][k][0];
            ulonglong2 p01 = csp[0], p23 = csp[1], p45 = csp[2], p67 = csp[3];
            u64 cs[7] = {p01.x, p01.y, p23.x, p23.y, p45.x, p45.y, p67.x};
#pragma unroll
            for (int d = 0; d < 7; d++) {
                FMA2(C[d], nb3, cs[d], C[d]);
                FMA2(D[d], nb0, cs[d], D[d]);
            }
        }

        float* st0 = s_u.stage[w][0];
        float* st1 = s_u.stage[w][1];
        float* st2 = s_u.stage[w][2];
        float* st3 = s_u.stage[w][3];
#pragma unroll
        for (int d = 0; d < 7; d++) {
            u64 v3; FMA2(v3, C[d], a3p, W[d]);
            float lo, hi;
            UNPACK2(lo, hi, v3);
            st0[1 + 7 * lane + d] = lo;
            st1[1 + 7 * lane + d] = hi;
            UNPACK2(lo, hi, D[d]);
            st2[1 + 7 * lane + d] = lo;
            st3[1 + 7 * lane + d] = hi;
        }
        __syncwarp();
        flush_chunk(out + OFF_QDDDOT + chunk0, st0, lane);
        flush_chunk(out + OFF_QDDDOT + chunk1, st1, lane);
        flush_chunk(out + OFF_Q      + chunk0, st2, lane);
        flush_chunk(out + OFF_Q      + chunk1, st3, lane);
        flush_chunk(out + OFF_TORQUE + chunk0, s_zero, lane);
        flush_chunk(out + OFF_TORQUE + chunk1, s_zero, lane);
        if (lane < 28) {
#pragma unroll
            for (int j = 0; j < 8; j++) {
                int t8 = 8 * lg + j;
                acc3 += huber_relu_dt(st0[1 + 7 * t8 + ld], limC, sdt[t8]);
                acc3 += huber_relu_dt(st1[1 + 7 * t8 + ld], limC, sdt[32 + t8]);
            }
        }
    }

    // ======== loss reduction: 4-lane groups per dof ========
    acc1 += __shfl_xor_sync(0xffffffffu, acc1, 1);
    acc1 += __shfl_xor_sync(0xffffffffu, acc1, 2);
    acc2 += __shfl_xor_sync(0xffffffffu, acc2, 1);
    acc2 += __shfl_xor_sync(0xffffffffu, acc2, 2);
    acc3 += __shfl_xor_sync(0xffffffffu, acc3, 1);
    acc3 += __shfl_xor_sync(0xffffffffu, acc3, 2);

    float tsum = 0.f;
    if (lane < 28 && (lane & 3) == 0) {
        atomicAdd(&out[OFF_QDOT_LOSS   + (size_t)b * NDOF + ld], acc1);
        atomicAdd(&out[OFF_QDDOT_LOSS  + (size_t)b * NDOF + ld], acc2);
        atomicAdd(&out[OFF_QDDDOT_LOSS + (size_t)b * NDOF + ld], acc3);
        tsum = acc1 + acc2 + acc3;
    }
    tsum += __shfl_xor_sync(0xffffffffu, tsum, 4);
    tsum += __shfl_xor_sync(0xffffffffu, tsum, 8);
    tsum += __shfl_xor_sync(0xffffffffu, tsum, 16);
    if (lane == 0) s_model[w] = tsum;
    __syncthreads();
    if (tid == 0) {
        float m = 0.0f;
#pragma unroll
        for (int ww = 0; ww < B_TILE; ww++) m += s_model[ww];
        atomicAdd(&out[OFF_MODEL], m);   // fused finalize
    }
}

// ---------------------------------------------------------------------------
extern "C" void kernel_launch(void* const* d_in, const int* in_sizes, int n_in,
                              void* d_out, int out_size)
{
    const float* q_cps  = (const float*)d_in[0];
    const float* t_cps  = (const float*)d_in[1];
    const float* N      = (const float*)d_in[2];
    const float* dN     = (const float*)d_in[3];
    const float* ddN    = (const float*)d_in[4];
    const float* dddN   = (const float*)d_in[5];
    const float* Nt     = (const float*)d_in[6];
    const float* dNt    = (const float*)d_in[7];
    const float* ddNt   = (const float*)d_in[8];
    const float* Ldot   = (const float*)d_in[9];
    const float* Lddot  = (const float*)d_in[10];
    const float* Ldddot = (const float*)d_in[11];
    // d_in[12] = torque_limits (unused: torque == 0 -> torque_loss == 0)

    float* out = (float*)d_out;

    // zero model_loss + all four loss regions (everything else written by fused_kernel)
    cudaMemsetAsync(out, 0, (size_t)OFF_Q * sizeof(float), 0);

    fused_kernel<<<3072, THR>>>(q_cps, t_cps, N, dN, ddN, dddN,
                                Nt, dNt, ddNt, Ldot, Lddot, Ldddot, out);
}

// round 16
// speedup vs baseline: 1.1553x; 1.1553x over previous
#include <cuda_runtime.h>
#include <cstddef>

typedef unsigned long long u64;

// Problem constants
#define NB   1024
#define NT   1024
#define KQ   15
#define KT   20
#define NDOF 7

// Output layout offsets (fp32 elements), total = 38,827,009
static constexpr size_t OFF_MODEL       = 0;
static constexpr size_t OFF_QDOT_LOSS   = 1;
static constexpr size_t OFF_QDDOT_LOSS  = 1 + 7168;
static constexpr size_t OFF_QDDDOT_LOSS = 1 + 2 * 7168;
static constexpr size_t OFF_TORQUE_LOSS = 1 + 3 * 7168;
static constexpr size_t OFF_Q           = 1 + 4 * 7168;           // 28673 (== 1 mod 4)
static constexpr size_t QTD             = (size_t)NB * NT * NDOF; // 7,340,032
static constexpr size_t OFF_QDOT        = OFF_Q + QTD;
static constexpr size_t OFF_QDDOT       = OFF_Q + 2 * QTD;
static constexpr size_t OFF_QDDDOT      = OFF_Q + 3 * QTD;
static constexpr size_t OFF_TORQUE      = OFF_Q + 4 * QTD;
static constexpr size_t OFF_T           = OFF_Q + 5 * QTD;
static constexpr size_t OFF_TCUM        = OFF_T + NB;
static constexpr size_t OFF_DT          = OFF_TCUM + (size_t)NB * NT;

// ---- packed f32x2 helpers -------------------------------------------------
#define PACK2(out, lo, hi) \
    asm("mov.b64 %0, {%1, %2};" : "=l"(out) : "r"(__float_as_uint(lo)), "r"(__float_as_uint(hi)))
#define UNPACK2(lo, hi, in) do { unsigned int _ulo, _uhi; \
    asm("mov.b64 {%0, %1}, %2;" : "=r"(_ulo), "=r"(_uhi) : "l"(in)); \
    lo = __uint_as_float(_ulo); hi = __uint_as_float(_uhi); } while (0)
#define FMA2(d, a, b, c) asm("fma.rn.f32x2 %0, %1, %2, %3;" : "=l"(d) : "l"(a), "l"(b), "l"(c))
#define MUL2(d, a, b)    asm("mul.rn.f32x2 %0, %1, %2;"     : "=l"(d) : "l"(a), "l"(b))

__device__ __forceinline__ float huber_relu_dt(float v, float lim, float dt) {
    // huber(relu(|v| - lim), delta=1) * dt, branchless
    float r = fmaxf(fabsf(v) - lim, 0.0f);
    float m = fminf(r, 1.0f);
    return (r - 0.5f * m) * m * dt;
}

// ---------------------------------------------------------------------------
// Flush a staged 224-float chunk (data at buf[1..224]) to g (g%4 floats == 1):
// 55x STG.128 body + 4 scalar edges.
// ---------------------------------------------------------------------------
__device__ __forceinline__ void flush_chunk(float* __restrict__ g,
                                            const float* __restrict__ buf,
                                            int lane)
{
    float4 x0 = *(const float4*)(buf + 4 * (lane + 1));
    *(float4*)(g + 4 * (lane + 1) - 1) = x0;
    if (lane < 23) {
        float4 x1 = *(const float4*)(buf + 4 * (lane + 33));
        *(float4*)(g + 4 * (lane + 33) - 1) = x1;
    }
    if (lane < 3)       g[lane] = buf[lane + 1];
    else if (lane == 3) g[223]  = buf[224];
}

// Zero variant: no smem read, stores zeros directly.
__device__ __forceinline__ void flush_zero_chunk(float* __restrict__ g, int lane)
{
    float4 z = make_float4(0.f, 0.f, 0.f, 0.f);
    *(float4*)(g + 4 * (lane + 1) - 1) = z;
    if (lane < 23)
        *(float4*)(g + 4 * (lane + 33) - 1) = z;
    if (lane < 3)       g[lane] = 0.f;
    else if (lane == 3) g[223]  = 0.f;
}

// ---------------------------------------------------------------------------
// Fused kernel, grid = 2048 blocks x 256 threads (R13 main body).
//   bid <  128 : "heavy" block -> t-tile 0, b-tile bid; afterwards also
//                computes dt / t_cumsum / t for its 8 batches (side work,
//                scheduled in wave 1 so it overlaps later main waves).
//   bid >= 128 : regular main block over the remaining 15 t-tiles.
// ---------------------------------------------------------------------------
#define T_TILE 64
#define B_TILE 8
#define THR    256

union SmemOverlay {
    float2 tbp[3][KT][32];            // 15360 B, prologue only
    float  stage[B_TILE][4][240];     // 30720 B, after sync (also side-Nt chunk)
};

__global__ __launch_bounds__(THR, 3)
void fused_kernel(const float* __restrict__ q_cps, const float* __restrict__ t_cps,
                  const float* __restrict__ N,   const float* __restrict__ dN,
                  const float* __restrict__ ddN, const float* __restrict__ dddN,
                  const float* __restrict__ Nt,  const float* __restrict__ dNt,
                  const float* __restrict__ ddNt,
                  const float* __restrict__ Ldot, const float* __restrict__ Lddot,
                  const float* __restrict__ Ldddot,
                  float* __restrict__ out)
{
    __shared__ float2 s_qbp[4][KQ][32];                 // [plane][k][lt-pair]
    __shared__ SmemOverlay s_u;                         // tbp (prologue) / stage
    __shared__ __align__(16) u64 s_qcd[B_TILE][KQ][8];  // dup q_cps pairs; slot 7 pad
    __shared__ __align__(16) u64 s_tcd[B_TILE][KT];     // dup t_cps pairs
    __shared__ float  s_lims[24];
    __shared__ float  s_dt[B_TILE][64];                 // per-warp dt per t
    __shared__ float  s_model[B_TILE];

    const int tid = threadIdx.x;
    const int bid = blockIdx.x;

    const bool heavy = (bid < 128);
    int ttile, btile;
    if (heavy) { ttile = 0; btile = bid; }
    else       { int m = bid - 128; ttile = 1 + (m % 15); btile = m / 15; }
    const int t0 = ttile * T_TILE;
    const int b0 = btile * B_TILE;

    {
        const float* qa[4] = {N, dN, ddN, dddN};
        for (int idx = tid; idx < 4 * KQ * 32; idx += THR) {
            int p = idx / (KQ * 32), r = idx % (KQ * 32);
            int k = r / 32, lt = r % 32;
            const float* src = qa[p];
            s_qbp[p][k][lt] = make_float2(src[(t0 + lt) * KQ + k],
                                          src[(t0 + lt + 32) * KQ + k]);
        }
        const float* ta[3] = {Nt, dNt, ddNt};
        for (int idx = tid; idx < 3 * KT * 32; idx += THR) {
            int p = idx / (KT * 32), r = idx % (KT * 32);
            int k = r / 32, lt = r % 32;
            const float* src = ta[p];
            s_u.tbp[p][k][lt] = make_float2(src[(t0 + lt) * KT + k],
                                            src[(t0 + lt + 32) * KT + k]);
        }
    }
    for (int idx = tid; idx < B_TILE * KQ * NDOF; idx += THR) {
        int w = idx / (KQ * NDOF), r = idx % (KQ * NDOF);
        float c = q_cps[(size_t)b0 * KQ * NDOF + idx];
        u64 p; PACK2(p, c, c);
        s_qcd[w][r / NDOF][r % NDOF] = p;
    }
    for (int idx = tid; idx < B_TILE * KT; idx += THR) {
        float c = t_cps[b0 * KT + idx];
        u64 p; PACK2(p, c, c);
        s_tcd[idx / KT][idx % KT] = p;
    }
    if (tid < 7) {
        s_lims[tid]      = Ldot[tid];
        s_lims[7 + tid]  = Lddot[tid];
        s_lims[14 + tid] = Ldddot[tid];
    }
    __syncthreads();

    const int lane = tid & 31;
    const int w    = tid >> 5;   // local batch 0..7
    const int b    = b0 + w;

    // --- fused time-spline evaluation (packed; reads s_u.tbp) ---
    u64 ap = 0, ddp = 0, dddp = 0;
#pragma unroll
    for (int k = 0; k < KT; k += 2) {
        ulonglong2 tc2 = *(const ulonglong2*)&s_tcd[w][k];  // broadcast LDS.128
        FMA2(ap,   *(const u64*)&s_u.tbp[0][k][lane],     tc2.x, ap);
        FMA2(ddp,  *(const u64*)&s_u.tbp[1][k][lane],     tc2.x, ddp);
        FMA2(dddp, *(const u64*)&s_u.tbp[2][k][lane],     tc2.x, dddp);
        FMA2(ap,   *(const u64*)&s_u.tbp[0][k + 1][lane], tc2.y, ap);
        FMA2(ddp,  *(const u64*)&s_u.tbp[1][k + 1][lane], tc2.y, ddp);
        FMA2(dddp, *(const u64*)&s_u.tbp[2][k + 1][lane], tc2.y, dddp);
    }
    // packed coefficients (ddp/dddp die here)
    u64 a2p; MUL2(a2p, ap, ap);
    u64 a3p; MUL2(a3p, a2p, ap);
    u64 c1p; MUL2(c1p, ddp, ap);
    u64 c2p; { u64 t; MUL2(t, ddp, a2p); u64 th; PACK2(th, 3.0f, 3.0f); MUL2(c2p, th, t); }
    u64 c3p; { u64 t; MUL2(t, ddp, ddp); u64 t2; MUL2(t2, t, ap); FMA2(c3p, a2p, dddp, t2); }
    {
        float a0, a1; UNPACK2(a0, a1, ap);
        s_dt[w][lane]      = 1.0f / (a0 * (float)NT);
        s_dt[w][32 + lane] = 1.0f / (a1 * (float)NT);
    }

    // per-lane loss constants (lanes 0..27: d = lane>>2, g = lane&3)
    const int ld = lane >> 2;
    const int lg = lane & 3;
    float limA = 0.f, limB = 0.f, limC = 0.f;
    if (lane < 28) { limA = s_lims[ld]; limB = s_lims[7 + ld]; limC = s_lims[14 + ld]; }
    float acc1 = 0.f, acc2 = 0.f, acc3 = 0.f;

    const float* sdt = s_dt[w];
    const size_t chunk0 = ((size_t)b * NT + t0) * NDOF;       // multiple of 224
    const size_t chunk1 = chunk0 + 224;

    u64 W[7];   // v3 partial: qdd*c2 + qd*c3, carried into phase 2

    // ======== Merged phase 1: qd & qdd ========
    {
        u64 A[7], B2[7];
#pragma unroll
        for (int d = 0; d < 7; d++) { A[d] = 0; B2[d] = 0; }
#pragma unroll
        for (int k = 0; k < KQ; k++) {
            u64 nb1 = *(const u64*)&s_qbp[1][k][lane];
            u64 nb2 = *(const u64*)&s_qbp[2][k][lane];
            const ulonglong2* csp = (const ulonglong2*)&s_qcd[w][k][0];
            ulonglong2 p01 = csp[0], p23 = csp[1], p45 = csp[2], p67 = csp[3];
            u64 cs[7] = {p01.x, p01.y, p23.x, p23.y, p45.x, p45.y, p67.x};
#pragma unroll
            for (int d = 0; d < 7; d++) {
                FMA2(A[d],  nb1, cs[d], A[d]);
                FMA2(B2[d], nb2, cs[d], B2[d]);
            }
        }
        // tbp must be fully consumed block-wide before staging overwrites it
        __syncthreads();

        float* st0 = s_u.stage[w][0];
        float* st1 = s_u.stage[w][1];
        float* st2 = s_u.stage[w][2];
        float* st3 = s_u.stage[w][3];
#pragma unroll
        for (int d = 0; d < 7; d++) {
            u64 v1; MUL2(v1, A[d], ap);
            u64 t1; MUL2(t1, A[d], c1p);
            u64 v2; FMA2(v2, B2[d], a2p, t1);
            u64 t2; MUL2(t2, A[d], c3p);
            FMA2(W[d], B2[d], c2p, t2);

            float lo, hi;
            UNPACK2(lo, hi, v1);
            st0[1 + 7 * lane + d] = lo;   // conflict-free (gcd(7,32)=1)
            st1[1 + 7 * lane + d] = hi;
            UNPACK2(lo, hi, v2);
            st2[1 + 7 * lane + d] = lo;
            st3[1 + 7 * lane + d] = hi;
        }
        __syncwarp();
        flush_chunk(out + OFF_QDOT  + chunk0, st0, lane);
        flush_chunk(out + OFF_QDOT  + chunk1, st1, lane);
        flush_chunk(out + OFF_QDDOT + chunk0, st2, lane);
        flush_chunk(out + OFF_QDDOT + chunk1, st3, lane);
        if (lane < 28) {
#pragma unroll
            for (int j = 0; j < 8; j++) {
                int t8 = 8 * lg + j;
                acc1 += huber_relu_dt(st0[1 + 7 * t8 + ld], limA, sdt[t8]);
                acc1 += huber_relu_dt(st1[1 + 7 * t8 + ld], limA, sdt[32 + t8]);
                acc2 += huber_relu_dt(st2[1 + 7 * t8 + ld], limB, sdt[t8]);
                acc2 += huber_relu_dt(st3[1 + 7 * t8 + ld], limB, sdt[32 + t8]);
            }
        }
        __syncwarp();
    }

    // ======== Merged phase 2: qddd & q; torque zeros from registers ========
    {
        u64 C[7], D[7];
#pragma unroll
        for (int d = 0; d < 7; d++) { C[d] = 0; D[d] = 0; }
#pragma unroll
        for (int k = 0; k < KQ; k++) {
            u64 nb3 = *(const u64*)&s_qbp[3][k][lane];
            u64 nb0 = *(const u64*)&s_qbp[0][k][lane];
            const ulonglong2* csp = (const ulonglong2*)&s_qcd[w][k][0];
            ulonglong2 p01 = csp[0], p23 = csp[1], p45 = csp[2], p67 = csp[3];
            u64 cs[7] = {p01.x, p01.y, p23.x, p23.y, p45.x, p45.y, p67.x};
#pragma unroll
            for (int d = 0; d < 7; d++) {
                FMA2(C[d], nb3, cs[d], C[d]);
                FMA2(D[d], nb0, cs[d], D[d]);
            }
        }

        float* st0 = s_u.stage[w][0];
        float* st1 = s_u.stage[w][1];
        float* st2 = s_u.stage[w][2];
        float* st3 = s_u.stage[w][3];
#pragma unroll
        for (int d = 0; d < 7; d++) {
            u64 v3; FMA2(v3, C[d], a3p, W[d]);
            float lo, hi;
            UNPACK2(lo, hi, v3);
            st0[1 + 7 * lane + d] = lo;
            st1[1 + 7 * lane + d] = hi;
            UNPACK2(lo, hi, D[d]);
            st2[1 + 7 * lane + d] = lo;
            st3[1 + 7 * lane + d] = hi;
        }
        __syncwarp();
        flush_chunk(out + OFF_QDDDOT + chunk0, st0, lane);
        flush_chunk(out + OFF_QDDDOT + chunk1, st1, lane);
        flush_chunk(out + OFF_Q      + chunk0, st2, lane);
        flush_chunk(out + OFF_Q      + chunk1, st3, lane);
        flush_zero_chunk(out + OFF_TORQUE + chunk0, lane);
        flush_zero_chunk(out + OFF_TORQUE + chunk1, lane);
        if (lane < 28) {
#pragma unroll
            for (int j = 0; j < 8; j++) {
                int t8 = 8 * lg + j;
                acc3 += huber_relu_dt(st0[1 + 7 * t8 + ld], limC, sdt[t8]);
                acc3 += huber_relu_dt(st1[1 + 7 * t8 + ld], limC, sdt[32 + t8]);
            }
        }
    }

    // ======== loss reduction: 4-lane groups per dof ========
    acc1 += __shfl_xor_sync(0xffffffffu, acc1, 1);
    acc1 += __shfl_xor_sync(0xffffffffu, acc1, 2);
    acc2 += __shfl_xor_sync(0xffffffffu, acc2, 1);
    acc2 += __shfl_xor_sync(0xffffffffu, acc2, 2);
    acc3 += __shfl_xor_sync(0xffffffffu, acc3, 1);
    acc3 += __shfl_xor_sync(0xffffffffu, acc3, 2);

    float tsum = 0.f;
    if (lane < 28 && (lane & 3) == 0) {
        atomicAdd(&out[OFF_QDOT_LOSS   + (size_t)b * NDOF + ld], acc1);
        atomicAdd(&out[OFF_QDDOT_LOSS  + (size_t)b * NDOF + ld], acc2);
        atomicAdd(&out[OFF_QDDDOT_LOSS + (size_t)b * NDOF + ld], acc3);
        tsum = acc1 + acc2 + acc3;
    }
    tsum += __shfl_xor_sync(0xffffffffu, tsum, 4);
    tsum += __shfl_xor_sync(0xffffffffu, tsum, 8);
    tsum += __shfl_xor_sync(0xffffffffu, tsum, 16);
    if (lane == 0) s_model[w] = tsum;
    __syncthreads();
    if (tid == 0) {
        float m = 0.0f;
#pragma unroll
        for (int ww = 0; ww < B_TILE; ww++) m += s_model[ww];
        atomicAdd(&out[OFF_MODEL], m);   // fused finalize
    }

    // ======== SIDE WORK (heavy blocks only, wave 1): dt + cumsum + t ========
    if (heavy) {
        // tc for this warp's batch, from s_tcd low halves (20 LDS.64, once)
        float tcr[KT];
#pragma unroll
        for (int k = 0; k < KT; k++) {
            float lo, hi; UNPACK2(lo, hi, s_tcd[w][k]);
            tcr[k] = lo;
        }
        float* sNtf = &s_u.stage[0][0][0];   // 32x21 chunk buffer (stage is dead)
        float carry = 0.0f;

        for (int c = 0; c < 32; c++) {
            __syncthreads();   // previous chunk fully consumed
            // cooperative, fully coalesced fill: Nt[640*c .. 640*c+640)
            for (int idx = tid; idx < 32 * KT; idx += THR)
                sNtf[(idx / KT) * 21 + (idx % KT)] = Nt[640 * c + idx];
            __syncthreads();

            float a = 0.0f;
#pragma unroll
            for (int k = 0; k < KT; k++)
                a = fmaf(sNtf[lane * 21 + k], tcr[k], a);   // stride-21: conflict-free
            float dtv = 1.0f / (a * (float)NT);

            // inclusive warp scan + carry
            float v = dtv;
#pragma unroll
            for (int off = 1; off < 32; off <<= 1) {
                float u = __shfl_up_sync(0xffffffffu, v, off);
                if (lane >= off) v += u;
            }
            v += carry;
            const size_t row = (size_t)b * NT + 32 * c + lane;
            out[OFF_DT   + row] = dtv;
            out[OFF_TCUM + row] = v;
            carry = __shfl_sync(0xffffffffu, v, 31);
        }
        if (lane == 0) out[OFF_T + b] = carry;
    }
}

// ---------------------------------------------------------------------------
extern "C" void kernel_launch(void* const* d_in, const int* in_sizes, int n_in,
                              void* d_out, int out_size)
{
    const float* q_cps  = (const float*)d_in[0];
    const float* t_cps  = (const float*)d_in[1];
    const float* N      = (const float*)d_in[2];
    const float* dN     = (const float*)d_in[3];
    const float* ddN    = (const float*)d_in[4];
    const float* dddN   = (const float*)d_in[5];
    const float* Nt     = (const float*)d_in[6];
    const float* dNt    = (const float*)d_in[7];
    const float* ddNt   = (const float*)d_in[8];
    const float* Ldot   = (const float*)d_in[9];
    const float* Lddot  = (const float*)d_in[10];
    const float* Ldddot = (const float*)d_in[11];
    // d_in[12] = torque_limits (unused: torque == 0 -> torque_loss == 0)

    float* out = (float*)d_out;

    // zero model_loss + all four loss regions (everything else written by fused_kernel)
    cudaMemsetAsync(out, 0, (size_t)OFF_Q * sizeof(float), 0);

    fused_kernel<<<2048, THR>>>(q_cps, t_cps, N, dN, ddN, dddN,
                                Nt, dNt, ddNt, Ldot, Lddot, Ldddot, out);
}